// round 1
// baseline (speedup 1.0000x reference)
#include <cuda_runtime.h>
#include <math.h>

#define D_MODEL 1024
#define NHEADS  16
#define HDIM    64
#define BB      2
#define LL      2048
#define MROWS   (BB * LL)   // 4096

// ---------------- scratch (allocation-free rule: __device__ globals) ---------
__device__ float g_Q[MROWS * D_MODEL];
__device__ float g_K[MROWS * D_MODEL];
__device__ float g_V[MROWS * D_MODEL];
__device__ float g_CTX[MROWS * D_MODEL];

// ---------------------------------------------------------------------------
// GEMM: C[M,N] = A[M,K] @ W[N,K]^T (+ bias). M=4096, N=K=1024, all divisible.
// 128x128 tile, BK=8, 256 threads, 8x8 micro-tile per thread.
// ---------------------------------------------------------------------------
template <bool HAS_BIAS>
__global__ __launch_bounds__(256) void gemm_xwT(
    const float* __restrict__ A, const float* __restrict__ W,
    const float* __restrict__ bias, float* __restrict__ C)
{
    const int K = D_MODEL;
    const int N = D_MODEL;
    __shared__ float As[8][128];
    __shared__ float Ws[8][128];

    const int t   = threadIdx.x;
    const int tx  = t & 15;
    const int ty  = t >> 4;
    const int row0 = blockIdx.y * 128;
    const int col0 = blockIdx.x * 128;

    const int lr = t >> 1;          // 0..127
    const int lk = (t & 1) * 4;     // 0 or 4

    const float* Aptr = A + (size_t)(row0 + lr) * K + lk;
    const float* Wptr = W + (size_t)(col0 + lr) * K + lk;

    float acc[8][8];
#pragma unroll
    for (int i = 0; i < 8; i++)
#pragma unroll
        for (int j = 0; j < 8; j++) acc[i][j] = 0.f;

    for (int k0 = 0; k0 < K; k0 += 8) {
        float4 av = *(const float4*)(Aptr + k0);
        float4 wv = *(const float4*)(Wptr + k0);
        __syncthreads();
        As[lk + 0][lr] = av.x; As[lk + 1][lr] = av.y;
        As[lk + 2][lr] = av.z; As[lk + 3][lr] = av.w;
        Ws[lk + 0][lr] = wv.x; Ws[lk + 1][lr] = wv.y;
        Ws[lk + 2][lr] = wv.z; Ws[lk + 3][lr] = wv.w;
        __syncthreads();
#pragma unroll
        for (int kk = 0; kk < 8; kk++) {
            float a[8], b[8];
            *(float4*)(a)     = *(const float4*)&As[kk][ty * 8];
            *(float4*)(a + 4) = *(const float4*)&As[kk][ty * 8 + 4];
            *(float4*)(b)     = *(const float4*)&Ws[kk][tx * 8];
            *(float4*)(b + 4) = *(const float4*)&Ws[kk][tx * 8 + 4];
#pragma unroll
            for (int i = 0; i < 8; i++)
#pragma unroll
                for (int j = 0; j < 8; j++)
                    acc[i][j] += a[i] * b[j];
        }
    }

#pragma unroll
    for (int i = 0; i < 8; i++) {
        float* cp = C + (size_t)(row0 + ty * 8 + i) * N + col0 + tx * 8;
#pragma unroll
        for (int j4 = 0; j4 < 8; j4 += 4) {
            float4 o;
            o.x = acc[i][j4 + 0]; o.y = acc[i][j4 + 1];
            o.z = acc[i][j4 + 2]; o.w = acc[i][j4 + 3];
            if (HAS_BIAS) {
                const float* bp = bias + col0 + tx * 8 + j4;
                o.x += bp[0]; o.y += bp[1]; o.z += bp[2]; o.w += bp[3];
            }
            *(float4*)(cp + j4) = o;
        }
    }
}

// ---------------------------------------------------------------------------
// Fused flash-style attention. One CTA = (b, h, 64-row q tile).
// 256 threads, thread (ty,tx) owns a 4x4 micro-tile of the 64x64 S/P/O tiles.
// ---------------------------------------------------------------------------
#define PAD 68
#define ATT_SMEM (4 * 64 * PAD * 4 + 64 * 4)

__global__ __launch_bounds__(256) void attn_kernel(const int* __restrict__ mask)
{
    extern __shared__ float smem[];
    float* Qs = smem;                 // [64][PAD]  (row, d)
    float* Ks = Qs + 64 * PAD;        // [64][PAD]  TRANSPOSED: (d, kv)
    float* Vs = Ks + 64 * PAD;        // [64][PAD]  (kv, d)
    float* Ps = Vs + 64 * PAD;        // [64][PAD]  (row, kv)
    int*   mk_s = (int*)(Ps + 64 * PAD);  // [64]

    const int t  = threadIdx.x;
    const int tx = t & 15;
    const int ty = t >> 4;
    const int q0 = blockIdx.x * 64;
    const int h  = blockIdx.y;
    const int b  = blockIdx.z;
    const float scale = 0.125f;   // 1/sqrt(64)

    // load Q tile
    const float* Qg = g_Q + (size_t)(b * LL + q0) * D_MODEL + h * HDIM;
#pragma unroll
    for (int i = 0; i < 4; i++) {
        int idx = t + i * 256;
        int r = idx >> 4;
        int c = (idx & 15) * 4;
        *(float4*)&Qs[r * PAD + c] = *(const float4*)(Qg + (size_t)r * D_MODEL + c);
    }

    float m_[4], l_[4], O[4][4];
#pragma unroll
    for (int i = 0; i < 4; i++) {
        m_[i] = -1e30f; l_[i] = 0.f;
#pragma unroll
        for (int j = 0; j < 4; j++) O[i][j] = 0.f;
    }

    for (int kt = 0; kt < LL / 64; kt++) {
        const int kv0 = kt * 64;
        __syncthreads();   // previous iteration's Ps/Vs reads complete
        const float* Kg = g_K + (size_t)(b * LL + kv0) * D_MODEL + h * HDIM;
        const float* Vg = g_V + (size_t)(b * LL + kv0) * D_MODEL + h * HDIM;
#pragma unroll
        for (int i = 0; i < 4; i++) {
            int idx = t + i * 256;
            int r = idx >> 4;
            int c = (idx & 15) * 4;
            float4 k4 = *(const float4*)(Kg + (size_t)r * D_MODEL + c);
            Ks[(c + 0) * PAD + r] = k4.x;
            Ks[(c + 1) * PAD + r] = k4.y;
            Ks[(c + 2) * PAD + r] = k4.z;
            Ks[(c + 3) * PAD + r] = k4.w;
            *(float4*)&Vs[r * PAD + c] = *(const float4*)(Vg + (size_t)r * D_MODEL + c);
        }
        if (t < 64) mk_s[t] = mask[b * LL + kv0 + t];
        __syncthreads();

        // S = Q @ K^T  (inner dim = 64)
        float s[4][4];
#pragma unroll
        for (int i = 0; i < 4; i++)
#pragma unroll
            for (int j = 0; j < 4; j++) s[i][j] = 0.f;

#pragma unroll
        for (int d4 = 0; d4 < 16; d4++) {
            float aq[4][4], bk[4][4];
#pragma unroll
            for (int i = 0; i < 4; i++)
                *(float4*)aq[i] = *(const float4*)&Qs[(ty * 4 + i) * PAD + d4 * 4];
#pragma unroll
            for (int dd = 0; dd < 4; dd++)
                *(float4*)bk[dd] = *(const float4*)&Ks[(d4 * 4 + dd) * PAD + tx * 4];
#pragma unroll
            for (int i = 0; i < 4; i++)
#pragma unroll
                for (int dd = 0; dd < 4; dd++)
#pragma unroll
                    for (int j = 0; j < 4; j++)
                        s[i][j] += aq[i][dd] * bk[dd][j];
        }

        int mk[4];
#pragma unroll
        for (int j = 0; j < 4; j++) mk[j] = mk_s[tx * 4 + j];

        // online softmax per row
#pragma unroll
        for (int i = 0; i < 4; i++) {
            float mt = -1e30f;
#pragma unroll
            for (int j = 0; j < 4; j++) {
                s[i][j] = mk[j] ? s[i][j] * scale : -1e30f;
                mt = fmaxf(mt, s[i][j]);
            }
#pragma unroll
            for (int o = 8; o > 0; o >>= 1)
                mt = fmaxf(mt, __shfl_xor_sync(0xffffffffu, mt, o));
            float m_new = fmaxf(m_[i], mt);
            float sc = __expf(m_[i] - m_new);   // both -1e30 -> exp(0)=1; old=-1e30,new finite -> 0
            float rs = 0.f;
#pragma unroll
            for (int j = 0; j < 4; j++) {
                float p = mk[j] ? __expf(s[i][j] - m_new) : 0.f;
                s[i][j] = p;
                rs += p;
            }
#pragma unroll
            for (int o = 8; o > 0; o >>= 1)
                rs += __shfl_xor_sync(0xffffffffu, rs, o);
            l_[i] = l_[i] * sc + rs;
            m_[i] = m_new;
#pragma unroll
            for (int j = 0; j < 4; j++) O[i][j] *= sc;
            float4 pv;
            pv.x = s[i][0]; pv.y = s[i][1]; pv.z = s[i][2]; pv.w = s[i][3];
            *(float4*)&Ps[(ty * 4 + i) * PAD + tx * 4] = pv;
        }
        __syncthreads();

        // O += P @ V   (inner dim = 64 kv)
#pragma unroll
        for (int k4 = 0; k4 < 16; k4++) {
            float ap[4][4], bv[4][4];
#pragma unroll
            for (int i = 0; i < 4; i++)
                *(float4*)ap[i] = *(const float4*)&Ps[(ty * 4 + i) * PAD + k4 * 4];
#pragma unroll
            for (int kk = 0; kk < 4; kk++)
                *(float4*)bv[kk] = *(const float4*)&Vs[(k4 * 4 + kk) * PAD + tx * 4];
#pragma unroll
            for (int i = 0; i < 4; i++)
#pragma unroll
                for (int kk = 0; kk < 4; kk++)
#pragma unroll
                    for (int j = 0; j < 4; j++)
                        O[i][j] += ap[i][kk] * bv[kk][j];
        }
    }

    // epilogue: normalize, fully-masked rows -> 0 (reference NaN->0 path)
    float* Cg = g_CTX + (size_t)(b * LL + q0) * D_MODEL + h * HDIM;
#pragma unroll
    for (int i = 0; i < 4; i++) {
        float inv = (l_[i] > 0.f) ? (1.f / l_[i]) : 0.f;
        float4 o;
        o.x = O[i][0] * inv; o.y = O[i][1] * inv;
        o.z = O[i][2] * inv; o.w = O[i][3] * inv;
        *(float4*)(Cg + (size_t)(ty * 4 + i) * D_MODEL + tx * 4) = o;
    }
}

// ---------------------------------------------------------------------------
extern "C" void kernel_launch(void* const* d_in, const int* in_sizes, int n_in,
                              void* d_out, int out_size)
{
    const float* q    = (const float*)d_in[0];
    const float* k    = (const float*)d_in[1];
    const float* v    = (const float*)d_in[2];
    const int*   mask = (const int*)  d_in[3];
    const float* Wq   = (const float*)d_in[4];
    const float* Wk   = (const float*)d_in[5];
    const float* Wv   = (const float*)d_in[6];
    const float* Wo   = (const float*)d_in[7];
    const float* bo   = (const float*)d_in[8];
    float*       out  = (float*)d_out;

    float *gQ, *gK, *gV, *gC;
    cudaGetSymbolAddress((void**)&gQ, g_Q);
    cudaGetSymbolAddress((void**)&gK, g_K);
    cudaGetSymbolAddress((void**)&gV, g_V);
    cudaGetSymbolAddress((void**)&gC, g_CTX);

    cudaFuncSetAttribute(attn_kernel,
                         cudaFuncAttributeMaxDynamicSharedMemorySize, ATT_SMEM);

    dim3 gg(D_MODEL / 128, MROWS / 128);   // (8, 32)
    gemm_xwT<false><<<gg, 256>>>(q, Wq, nullptr, gQ);
    gemm_xwT<false><<<gg, 256>>>(k, Wk, nullptr, gK);
    gemm_xwT<false><<<gg, 256>>>(v, Wv, nullptr, gV);

    attn_kernel<<<dim3(LL / 64, NHEADS, BB), 256, ATT_SMEM>>>(mask);

    gemm_xwT<true><<<gg, 256>>>(gC, Wo, bo, out);
}

// round 8
// speedup vs baseline: 1.3640x; 1.3640x over previous
#include <cuda_runtime.h>
#include <cuda_bf16.h>
#include <cstdint>
#include <math.h>

#define D_MODEL 1024
#define NHEADS  16
#define HDIM    64
#define BB      2
#define LL      2048
#define MROWS   (BB * LL)   // 4096

// ---------------- scratch (allocation-free rule: __device__ globals) ---------
__device__ float g_Q[MROWS * D_MODEL];
__device__ float g_K[MROWS * D_MODEL];
__device__ float g_V[MROWS * D_MODEL];
__device__ float g_CTX[MROWS * D_MODEL];
__device__ __nv_bfloat16 g_Ahi[MROWS * D_MODEL];
__device__ __nv_bfloat16 g_Alo[MROWS * D_MODEL];
__device__ __nv_bfloat16 g_Whi[D_MODEL * D_MODEL];
__device__ __nv_bfloat16 g_Wlo[D_MODEL * D_MODEL];

// ---------------------------------------------------------------------------
// baseline-PTX helpers (sm_80-era: cp.async / ldmatrix / mma.sync — all legal
// on a compute_103 PTX target; tcgen05/TMA are NOT)
// ---------------------------------------------------------------------------
static __device__ __forceinline__ uint32_t smem_u32(const void* p) {
    uint32_t a;
    asm("{ .reg .u64 t; cvta.to.shared.u64 t, %1; cvt.u32.u64 %0, t; }"
        : "=r"(a) : "l"(p));
    return a;
}

static __device__ __forceinline__ void cp_async16(uint32_t saddr, const void* gaddr) {
    asm volatile("cp.async.cg.shared.global [%0], [%1], 16;" :: "r"(saddr), "l"(gaddr));
}
static __device__ __forceinline__ void cp_commit() {
    asm volatile("cp.async.commit_group;" ::: "memory");
}
template <int N>
static __device__ __forceinline__ void cp_wait() {
    asm volatile("cp.async.wait_group %0;" :: "n"(N) : "memory");
}

static __device__ __forceinline__ void ldm_x4(uint32_t* r, uint32_t saddr) {
    asm volatile("ldmatrix.sync.aligned.m8n8.x4.shared.b16 {%0,%1,%2,%3}, [%4];"
                 : "=r"(r[0]), "=r"(r[1]), "=r"(r[2]), "=r"(r[3]) : "r"(saddr));
}

static __device__ __forceinline__ void mma_bf16(float* c, const uint32_t* a,
                                                uint32_t b0, uint32_t b1) {
    asm volatile(
        "mma.sync.aligned.m16n8k16.row.col.f32.bf16.bf16.f32 "
        "{%0,%1,%2,%3}, {%4,%5,%6,%7}, {%8,%9}, {%0,%1,%2,%3};"
        : "+f"(c[0]), "+f"(c[1]), "+f"(c[2]), "+f"(c[3])
        : "r"(a[0]), "r"(a[1]), "r"(a[2]), "r"(a[3]), "r"(b0), "r"(b1));
}

// ---------------------------------------------------------------------------
// fp32 -> bf16 hi/lo split (for bf16x3 fp32-emulation GEMM)
// ---------------------------------------------------------------------------
__global__ void split_bf16(const float4* __restrict__ in,
                           __nv_bfloat162* __restrict__ hi,
                           __nv_bfloat162* __restrict__ lo, int n4)
{
    int i = blockIdx.x * blockDim.x + threadIdx.x;
    if (i >= n4) return;
    float4 x = in[i];
    __nv_bfloat16 h0 = __float2bfloat16(x.x), h1 = __float2bfloat16(x.y);
    __nv_bfloat16 h2 = __float2bfloat16(x.z), h3 = __float2bfloat16(x.w);
    __nv_bfloat16 l0 = __float2bfloat16(x.x - __bfloat162float(h0));
    __nv_bfloat16 l1 = __float2bfloat16(x.y - __bfloat162float(h1));
    __nv_bfloat16 l2 = __float2bfloat16(x.z - __bfloat162float(h2));
    __nv_bfloat16 l3 = __float2bfloat16(x.w - __bfloat162float(h3));
    hi[2 * i]     = __nv_bfloat162(h0, h1);
    hi[2 * i + 1] = __nv_bfloat162(h2, h3);
    lo[2 * i]     = __nv_bfloat162(l0, l1);
    lo[2 * i + 1] = __nv_bfloat162(l2, l3);
}

// ---------------------------------------------------------------------------
// HMMA GEMM: C[M=4096, N=1024] = A[M,K=1024] @ W[N,K]^T (+ bias)
// bf16x3: C = Ah*Wh + Ah*Wl + Al*Wh  (fp32 accum).
// CTA 128x128, BK=32, 8 warps (warp tile 32x64), cp.async double buffer.
// Smem stage layout (pitch 80B rows, 16B-aligned, conflict-free for ldmatrix):
//   A: op*10240 + row*80 + chunk*16          (rows = m, 128)
//   B: 20480 + op*10240 + row*80 + chunk*16  (rows = n, 128)
// Stage = 40960 B, 2 stages = 81920 B dynamic smem.
// ---------------------------------------------------------------------------
#define STAGE_B 40960
#define GSMEM   (2 * STAGE_B)

template <bool HAS_BIAS>
__global__ __launch_bounds__(256, 1) void hmma_gemm(
    const __nv_bfloat16* __restrict__ Ahi, const __nv_bfloat16* __restrict__ Alo,
    const __nv_bfloat16* __restrict__ Bhi, const __nv_bfloat16* __restrict__ Blo,
    float* __restrict__ C, const float* __restrict__ bias)
{
    extern __shared__ char sm[];
    const uint32_t sb = smem_u32(sm);
    const int t = threadIdx.x;
    const int lane = t & 31, wid = t >> 5;
    const int wm = wid & 3, wn = wid >> 2;       // 4x2 warp grid
    const int row0 = blockIdx.y * 128, col0 = blockIdx.x * 128;

    // ---- per-thread cp.async mapping: 8 x 16B chunks per stage ----
    // idx in [0,2048): part=idx>>10 (0=A,1=B), op=(idx>>9)&1, r=(idx>>2)&127, c=idx&3
    const __nv_bfloat16* srcA[2] = { Ahi + (size_t)row0 * 1024,
                                     Alo + (size_t)row0 * 1024 };
    const __nv_bfloat16* srcB[2] = { Bhi + (size_t)col0 * 1024,
                                     Blo + (size_t)col0 * 1024 };

    auto load_stage = [&](int s) {
        const int k0 = s * 32;
        const uint32_t sbase = sb + (s & 1) * STAGE_B;
#pragma unroll
        for (int i = 0; i < 8; i++) {
            int idx  = t + i * 256;
            int part = idx >> 10;
            int op   = (idx >> 9) & 1;
            int r    = (idx >> 2) & 127;
            int c    = idx & 3;
            const __nv_bfloat16* g =
                (part ? srcB[op] : srcA[op]) + (size_t)r * 1024 + k0 + c * 8;
            uint32_t sa = sbase + part * 20480 + op * 10240 + r * 80 + c * 16;
            cp_async16(sa, g);
        }
        cp_commit();
    };

    // ---- ldmatrix lane-address components ----
    // A (x4, m16k16): row = wm*32 + i*16 + (lane&15); +16B if lane>=16 (k8..15)
    const uint32_t a_lane = (uint32_t)((wm * 32 + (lane & 15)) * 80 + (lane >> 4) * 16);
    // B (x4, two n8k16 tiles): row = wn*64 + p*16 + (lane&7) + ((lane>>4)&1)*8;
    //                          +16B if (lane>>3)&1 (k8..15)
    const uint32_t b_lane = (uint32_t)((wn * 64 + (lane & 7) + ((lane >> 4) & 1) * 8) * 80
                                       + ((lane >> 3) & 1) * 16);

    float acc[2][8][4];
#pragma unroll
    for (int i = 0; i < 2; i++)
#pragma unroll
        for (int n = 0; n < 8; n++)
#pragma unroll
            for (int j = 0; j < 4; j++) acc[i][n][j] = 0.f;

    load_stage(0);

    for (int s = 0; s < 32; s++) {
        if (s + 1 < 32) { load_stage(s + 1); cp_wait<1>(); }
        else            { cp_wait<0>(); }
        __syncthreads();

        const uint32_t sbase = sb + (s & 1) * STAGE_B;
#pragma unroll
        for (int ks = 0; ks < 2; ks++) {
            const uint32_t ksb = ks * 32;   // 16 bf16 = 32 bytes
            uint32_t ah[2][4], al[2][4], bh[4][4], bl[4][4];
#pragma unroll
            for (int i = 0; i < 2; i++) {
                uint32_t base = sbase + a_lane + (uint32_t)(i * 16 * 80) + ksb;
                ldm_x4(ah[i], base);            // A hi (op 0)
                ldm_x4(al[i], base + 10240);    // A lo (op 1)
            }
#pragma unroll
            for (int p = 0; p < 4; p++) {
                uint32_t base = sbase + 20480 + b_lane + (uint32_t)(p * 16 * 80) + ksb;
                ldm_x4(bh[p], base);
                ldm_x4(bl[p], base + 10240);
            }
#pragma unroll
            for (int p = 0; p < 4; p++) {
#pragma unroll
                for (int i = 0; i < 2; i++) {
                    // Ah*Bh
                    mma_bf16(acc[i][2 * p],     ah[i], bh[p][0], bh[p][1]);
                    mma_bf16(acc[i][2 * p + 1], ah[i], bh[p][2], bh[p][3]);
                    // Ah*Bl
                    mma_bf16(acc[i][2 * p],     ah[i], bl[p][0], bl[p][1]);
                    mma_bf16(acc[i][2 * p + 1], ah[i], bl[p][2], bl[p][3]);
                    // Al*Bh
                    mma_bf16(acc[i][2 * p],     al[i], bh[p][0], bh[p][1]);
                    mma_bf16(acc[i][2 * p + 1], al[i], bh[p][2], bh[p][3]);
                }
            }
        }
        __syncthreads();
    }

    // ---- epilogue: c0,c1 -> (row lane/4, col (lane%4)*2); c2,c3 -> row+8 ----
    const int er = lane >> 2, ec = (lane & 3) * 2;
#pragma unroll
    for (int i = 0; i < 2; i++) {
        const int rbase = row0 + wm * 32 + i * 16 + er;
#pragma unroll
        for (int n = 0; n < 8; n++) {
            const int cc = col0 + wn * 64 + n * 8 + ec;
            float b0 = 0.f, b1 = 0.f;
            if (HAS_BIAS) { b0 = bias[cc]; b1 = bias[cc + 1]; }
            float2 lo_v = make_float2(acc[i][n][0] + b0, acc[i][n][1] + b1);
            float2 hi_v = make_float2(acc[i][n][2] + b0, acc[i][n][3] + b1);
            *(float2*)(C + (size_t)rbase * 1024 + cc)       = lo_v;
            *(float2*)(C + (size_t)(rbase + 8) * 1024 + cc) = hi_v;
        }
    }
}

// ---------------------------------------------------------------------------
// Fused flash-style attention (fp32, unchanged from round 1).
// ---------------------------------------------------------------------------
#define PAD 68
#define ATT_SMEM (4 * 64 * PAD * 4 + 64 * 4)

__global__ __launch_bounds__(256) void attn_kernel(const int* __restrict__ mask)
{
    extern __shared__ float smem[];
    float* Qs = smem;
    float* Ks = Qs + 64 * PAD;
    float* Vs = Ks + 64 * PAD;
    float* Ps = Vs + 64 * PAD;
    int*   mk_s = (int*)(Ps + 64 * PAD);

    const int t  = threadIdx.x;
    const int tx = t & 15;
    const int ty = t >> 4;
    const int q0 = blockIdx.x * 64;
    const int h  = blockIdx.y;
    const int b  = blockIdx.z;
    const float scale = 0.125f;

    const float* Qg = g_Q + (size_t)(b * LL + q0) * D_MODEL + h * HDIM;
#pragma unroll
    for (int i = 0; i < 4; i++) {
        int idx = t + i * 256;
        int r = idx >> 4;
        int c = (idx & 15) * 4;
        *(float4*)&Qs[r * PAD + c] = *(const float4*)(Qg + (size_t)r * D_MODEL + c);
    }

    float m_[4], l_[4], O[4][4];
#pragma unroll
    for (int i = 0; i < 4; i++) {
        m_[i] = -1e30f; l_[i] = 0.f;
#pragma unroll
        for (int j = 0; j < 4; j++) O[i][j] = 0.f;
    }

    for (int kt = 0; kt < LL / 64; kt++) {
        const int kv0 = kt * 64;
        __syncthreads();
        const float* Kg = g_K + (size_t)(b * LL + kv0) * D_MODEL + h * HDIM;
        const float* Vg = g_V + (size_t)(b * LL + kv0) * D_MODEL + h * HDIM;
#pragma unroll
        for (int i = 0; i < 4; i++) {
            int idx = t + i * 256;
            int r = idx >> 4;
            int c = (idx & 15) * 4;
            float4 k4 = *(const float4*)(Kg + (size_t)r * D_MODEL + c);
            Ks[(c + 0) * PAD + r] = k4.x;
            Ks[(c + 1) * PAD + r] = k4.y;
            Ks[(c + 2) * PAD + r] = k4.z;
            Ks[(c + 3) * PAD + r] = k4.w;
            *(float4*)&Vs[r * PAD + c] = *(const float4*)(Vg + (size_t)r * D_MODEL + c);
        }
        if (t < 64) mk_s[t] = mask[b * LL + kv0 + t];
        __syncthreads();

        float s[4][4];
#pragma unroll
        for (int i = 0; i < 4; i++)
#pragma unroll
            for (int j = 0; j < 4; j++) s[i][j] = 0.f;

#pragma unroll
        for (int d4 = 0; d4 < 16; d4++) {
            float aq[4][4], bk[4][4];
#pragma unroll
            for (int i = 0; i < 4; i++)
                *(float4*)aq[i] = *(const float4*)&Qs[(ty * 4 + i) * PAD + d4 * 4];
#pragma unroll
            for (int dd = 0; dd < 4; dd++)
                *(float4*)bk[dd] = *(const float4*)&Ks[(d4 * 4 + dd) * PAD + tx * 4];
#pragma unroll
            for (int i = 0; i < 4; i++)
#pragma unroll
                for (int dd = 0; dd < 4; dd++)
#pragma unroll
                    for (int j = 0; j < 4; j++)
                        s[i][j] += aq[i][dd] * bk[dd][j];
        }

        int mk[4];
#pragma unroll
        for (int j = 0; j < 4; j++) mk[j] = mk_s[tx * 4 + j];

#pragma unroll
        for (int i = 0; i < 4; i++) {
            float mt = -1e30f;
#pragma unroll
            for (int j = 0; j < 4; j++) {
                s[i][j] = mk[j] ? s[i][j] * scale : -1e30f;
                mt = fmaxf(mt, s[i][j]);
            }
#pragma unroll
            for (int o = 8; o > 0; o >>= 1)
                mt = fmaxf(mt, __shfl_xor_sync(0xffffffffu, mt, o));
            float m_new = fmaxf(m_[i], mt);
            float sc = __expf(m_[i] - m_new);
            float rs = 0.f;
#pragma unroll
            for (int j = 0; j < 4; j++) {
                float p = mk[j] ? __expf(s[i][j] - m_new) : 0.f;
                s[i][j] = p;
                rs += p;
            }
#pragma unroll
            for (int o = 8; o > 0; o >>= 1)
                rs += __shfl_xor_sync(0xffffffffu, rs, o);
            l_[i] = l_[i] * sc + rs;
            m_[i] = m_new;
#pragma unroll
            for (int j = 0; j < 4; j++) O[i][j] *= sc;
            float4 pv;
            pv.x = s[i][0]; pv.y = s[i][1]; pv.z = s[i][2]; pv.w = s[i][3];
            *(float4*)&Ps[(ty * 4 + i) * PAD + tx * 4] = pv;
        }
        __syncthreads();

#pragma unroll
        for (int k4 = 0; k4 < 16; k4++) {
            float ap[4][4], bv[4][4];
#pragma unroll
            for (int i = 0; i < 4; i++)
                *(float4*)ap[i] = *(const float4*)&Ps[(ty * 4 + i) * PAD + k4 * 4];
#pragma unroll
            for (int kk = 0; kk < 4; kk++)
                *(float4*)bv[kk] = *(const float4*)&Vs[(k4 * 4 + kk) * PAD + tx * 4];
#pragma unroll
            for (int i = 0; i < 4; i++)
#pragma unroll
                for (int kk = 0; kk < 4; kk++)
#pragma unroll
                    for (int j = 0; j < 4; j++)
                        O[i][j] += ap[i][kk] * bv[kk][j];
        }
    }

    float* Cg = g_CTX + (size_t)(b * LL + q0) * D_MODEL + h * HDIM;
#pragma unroll
    for (int i = 0; i < 4; i++) {
        float inv = (l_[i] > 0.f) ? (1.f / l_[i]) : 0.f;
        float4 o;
        o.x = O[i][0] * inv; o.y = O[i][1] * inv;
        o.z = O[i][2] * inv; o.w = O[i][3] * inv;
        *(float4*)(Cg + (size_t)(ty * 4 + i) * D_MODEL + tx * 4) = o;
    }
}

// ---------------------------------------------------------------------------
extern "C" void kernel_launch(void* const* d_in, const int* in_sizes, int n_in,
                              void* d_out, int out_size)
{
    const float* q    = (const float*)d_in[0];
    const float* k    = (const float*)d_in[1];
    const float* v    = (const float*)d_in[2];
    const int*   mask = (const int*)  d_in[3];
    const float* Wq   = (const float*)d_in[4];
    const float* Wk   = (const float*)d_in[5];
    const float* Wv   = (const float*)d_in[6];
    const float* Wo   = (const float*)d_in[7];
    const float* bo   = (const float*)d_in[8];
    float*       out  = (float*)d_out;

    float *gQ, *gK, *gV, *gC;
    __nv_bfloat16 *gAhi, *gAlo, *gWhi, *gWlo;
    cudaGetSymbolAddress((void**)&gQ, g_Q);
    cudaGetSymbolAddress((void**)&gK, g_K);
    cudaGetSymbolAddress((void**)&gV, g_V);
    cudaGetSymbolAddress((void**)&gC, g_CTX);
    cudaGetSymbolAddress((void**)&gAhi, g_Ahi);
    cudaGetSymbolAddress((void**)&gAlo, g_Alo);
    cudaGetSymbolAddress((void**)&gWhi, g_Whi);
    cudaGetSymbolAddress((void**)&gWlo, g_Wlo);

    cudaFuncSetAttribute(attn_kernel,
                         cudaFuncAttributeMaxDynamicSharedMemorySize, ATT_SMEM);
    cudaFuncSetAttribute(hmma_gemm<false>,
                         cudaFuncAttributeMaxDynamicSharedMemorySize, GSMEM);
    cudaFuncSetAttribute(hmma_gemm<true>,
                         cudaFuncAttributeMaxDynamicSharedMemorySize, GSMEM);

    const int n4i = MROWS * D_MODEL / 4;
    const int n4w = D_MODEL * D_MODEL / 4;
    dim3 gg(D_MODEL / 128, MROWS / 128);   // (8, 32) = 256 CTAs

    // Q projection
    split_bf16<<<n4i / 256, 256>>>((const float4*)q,
        (__nv_bfloat162*)gAhi, (__nv_bfloat162*)gAlo, n4i);
    split_bf16<<<n4w / 256, 256>>>((const float4*)Wq,
        (__nv_bfloat162*)gWhi, (__nv_bfloat162*)gWlo, n4w);
    hmma_gemm<false><<<gg, 256, GSMEM>>>(gAhi, gAlo, gWhi, gWlo, gQ, nullptr);

    // K projection
    split_bf16<<<n4i / 256, 256>>>((const float4*)k,
        (__nv_bfloat162*)gAhi, (__nv_bfloat162*)gAlo, n4i);
    split_bf16<<<n4w / 256, 256>>>((const float4*)Wk,
        (__nv_bfloat162*)gWhi, (__nv_bfloat162*)gWlo, n4w);
    hmma_gemm<false><<<gg, 256, GSMEM>>>(gAhi, gAlo, gWhi, gWlo, gK, nullptr);

    // V projection
    split_bf16<<<n4i / 256, 256>>>((const float4*)v,
        (__nv_bfloat162*)gAhi, (__nv_bfloat162*)gAlo, n4i);
    split_bf16<<<n4w / 256, 256>>>((const float4*)Wv,
        (__nv_bfloat162*)gWhi, (__nv_bfloat162*)gWlo, n4w);
    hmma_gemm<false><<<gg, 256, GSMEM>>>(gAhi, gAlo, gWhi, gWlo, gV, nullptr);

    // attention
    attn_kernel<<<dim3(LL / 64, NHEADS, BB), 256, ATT_SMEM>>>(mask);

    // output projection
    split_bf16<<<n4i / 256, 256>>>((const float4*)gC,
        (__nv_bfloat162*)gAhi, (__nv_bfloat162*)gAlo, n4i);
    split_bf16<<<n4w / 256, 256>>>((const float4*)Wo,
        (__nv_bfloat162*)gWhi, (__nv_bfloat162*)gWlo, n4w);
    hmma_gemm<true><<<gg, 256, GSMEM>>>(gAhi, gAlo, gWhi, gWlo, out, bo);
}

// round 11
// speedup vs baseline: 2.6044x; 1.9094x over previous
#include <cuda_runtime.h>
#include <cuda_bf16.h>
#include <cstdint>
#include <math.h>

#define D_MODEL 1024
#define NHEADS  16
#define HDIM    64
#define BB      2
#define LL      2048
#define MROWS   (BB * LL)   // 4096

// ---------------- scratch (allocation-free rule: __device__ globals) ---------
__device__ __nv_bfloat16 g_Ahi[MROWS * D_MODEL];
__device__ __nv_bfloat16 g_Alo[MROWS * D_MODEL];
__device__ __nv_bfloat16 g_Whi[D_MODEL * D_MODEL];
__device__ __nv_bfloat16 g_Wlo[D_MODEL * D_MODEL];
__device__ __nv_bfloat16 g_Qh[MROWS * D_MODEL];
__device__ __nv_bfloat16 g_Ql[MROWS * D_MODEL];
__device__ __nv_bfloat16 g_Kh[MROWS * D_MODEL];
__device__ __nv_bfloat16 g_Kl[MROWS * D_MODEL];
__device__ __nv_bfloat16 g_Vh[MROWS * D_MODEL];
__device__ __nv_bfloat16 g_Vl[MROWS * D_MODEL];

// ---------------------------------------------------------------------------
// baseline-PTX helpers (sm_80-era; tcgen05/TMA are rejected at compute_103)
// ---------------------------------------------------------------------------
static __device__ __forceinline__ uint32_t smem_u32(const void* p) {
    uint32_t a;
    asm("{ .reg .u64 t; cvta.to.shared.u64 t, %1; cvt.u32.u64 %0, t; }"
        : "=r"(a) : "l"(p));
    return a;
}
static __device__ __forceinline__ void cp_async16(uint32_t saddr, const void* gaddr) {
    asm volatile("cp.async.cg.shared.global [%0], [%1], 16;" :: "r"(saddr), "l"(gaddr));
}
static __device__ __forceinline__ void cp_commit() {
    asm volatile("cp.async.commit_group;" ::: "memory");
}
template <int N>
static __device__ __forceinline__ void cp_wait() {
    asm volatile("cp.async.wait_group %0;" :: "n"(N) : "memory");
}
static __device__ __forceinline__ void ldm_x4(uint32_t* r, uint32_t saddr) {
    asm volatile("ldmatrix.sync.aligned.m8n8.x4.shared.b16 {%0,%1,%2,%3}, [%4];"
                 : "=r"(r[0]), "=r"(r[1]), "=r"(r[2]), "=r"(r[3]) : "r"(saddr));
}
static __device__ __forceinline__ void ldm_x4_t(uint32_t* r, uint32_t saddr) {
    asm volatile("ldmatrix.sync.aligned.m8n8.x4.trans.shared.b16 {%0,%1,%2,%3}, [%4];"
                 : "=r"(r[0]), "=r"(r[1]), "=r"(r[2]), "=r"(r[3]) : "r"(saddr));
}
static __device__ __forceinline__ void mma_bf16(float* c, const uint32_t* a,
                                                uint32_t b0, uint32_t b1) {
    asm volatile(
        "mma.sync.aligned.m16n8k16.row.col.f32.bf16.bf16.f32 "
        "{%0,%1,%2,%3}, {%4,%5,%6,%7}, {%8,%9}, {%0,%1,%2,%3};"
        : "+f"(c[0]), "+f"(c[1]), "+f"(c[2]), "+f"(c[3])
        : "r"(a[0]), "r"(a[1]), "r"(a[2]), "r"(a[3]), "r"(b0), "r"(b1));
}

// ---------------------------------------------------------------------------
// fp32 -> bf16 hi/lo split (inputs & weights)
// ---------------------------------------------------------------------------
__global__ void split_bf16(const float4* __restrict__ in,
                           __nv_bfloat162* __restrict__ hi,
                           __nv_bfloat162* __restrict__ lo, int n4)
{
    int i = blockIdx.x * blockDim.x + threadIdx.x;
    if (i >= n4) return;
    float4 x = in[i];
    __nv_bfloat16 h0 = __float2bfloat16(x.x), h1 = __float2bfloat16(x.y);
    __nv_bfloat16 h2 = __float2bfloat16(x.z), h3 = __float2bfloat16(x.w);
    __nv_bfloat16 l0 = __float2bfloat16(x.x - __bfloat162float(h0));
    __nv_bfloat16 l1 = __float2bfloat16(x.y - __bfloat162float(h1));
    __nv_bfloat16 l2 = __float2bfloat16(x.z - __bfloat162float(h2));
    __nv_bfloat16 l3 = __float2bfloat16(x.w - __bfloat162float(h3));
    hi[2 * i]     = __nv_bfloat162(h0, h1);
    hi[2 * i + 1] = __nv_bfloat162(h2, h3);
    lo[2 * i]     = __nv_bfloat162(l0, l1);
    lo[2 * i + 1] = __nv_bfloat162(l2, l3);
}

// ---------------------------------------------------------------------------
// HMMA GEMM (bf16x3): C = Ah*Wh + Ah*Wl + Al*Wh.  CTA 128x128, BK=32, 8 warps.
// SPLIT_OUT: write hi/lo bf16 outputs (feeds next GEMM/attention directly).
// ---------------------------------------------------------------------------
#define STAGE_B 40960
#define GSMEM   (2 * STAGE_B)

template <bool HAS_BIAS, bool SPLIT_OUT>
__global__ __launch_bounds__(256, 1) void hmma_gemm(
    const __nv_bfloat16* __restrict__ Ahi, const __nv_bfloat16* __restrict__ Alo,
    const __nv_bfloat16* __restrict__ Bhi, const __nv_bfloat16* __restrict__ Blo,
    float* __restrict__ C, __nv_bfloat16* __restrict__ Chi,
    __nv_bfloat16* __restrict__ Clo, const float* __restrict__ bias)
{
    extern __shared__ char sm[];
    const uint32_t sb = smem_u32(sm);
    const int t = threadIdx.x;
    const int lane = t & 31, wid = t >> 5;
    const int wm = wid & 3, wn = wid >> 2;
    const int row0 = blockIdx.y * 128, col0 = blockIdx.x * 128;

    const __nv_bfloat16* srcA[2] = { Ahi + (size_t)row0 * 1024,
                                     Alo + (size_t)row0 * 1024 };
    const __nv_bfloat16* srcB[2] = { Bhi + (size_t)col0 * 1024,
                                     Blo + (size_t)col0 * 1024 };

    auto load_stage = [&](int s) {
        const int k0 = s * 32;
        const uint32_t sbase = sb + (s & 1) * STAGE_B;
#pragma unroll
        for (int i = 0; i < 8; i++) {
            int idx  = t + i * 256;
            int part = idx >> 10;
            int op   = (idx >> 9) & 1;
            int r    = (idx >> 2) & 127;
            int c    = idx & 3;
            const __nv_bfloat16* g =
                (part ? srcB[op] : srcA[op]) + (size_t)r * 1024 + k0 + c * 8;
            uint32_t sa = sbase + part * 20480 + op * 10240 + r * 80 + c * 16;
            cp_async16(sa, g);
        }
        cp_commit();
    };

    const uint32_t a_lane = (uint32_t)((wm * 32 + (lane & 15)) * 80 + (lane >> 4) * 16);
    const uint32_t b_lane = (uint32_t)((wn * 64 + (lane & 7) + ((lane >> 4) & 1) * 8) * 80
                                       + ((lane >> 3) & 1) * 16);

    float acc[2][8][4];
#pragma unroll
    for (int i = 0; i < 2; i++)
#pragma unroll
        for (int n = 0; n < 8; n++)
#pragma unroll
            for (int j = 0; j < 4; j++) acc[i][n][j] = 0.f;

    load_stage(0);

    for (int s = 0; s < 32; s++) {
        if (s + 1 < 32) { load_stage(s + 1); cp_wait<1>(); }
        else            { cp_wait<0>(); }
        __syncthreads();

        const uint32_t sbase = sb + (s & 1) * STAGE_B;
#pragma unroll
        for (int ks = 0; ks < 2; ks++) {
            const uint32_t ksb = ks * 32;
            uint32_t ah[2][4], al[2][4], bh[4][4], bl[4][4];
#pragma unroll
            for (int i = 0; i < 2; i++) {
                uint32_t base = sbase + a_lane + (uint32_t)(i * 16 * 80) + ksb;
                ldm_x4(ah[i], base);
                ldm_x4(al[i], base + 10240);
            }
#pragma unroll
            for (int p = 0; p < 4; p++) {
                uint32_t base = sbase + 20480 + b_lane + (uint32_t)(p * 16 * 80) + ksb;
                ldm_x4(bh[p], base);
                ldm_x4(bl[p], base + 10240);
            }
#pragma unroll
            for (int p = 0; p < 4; p++) {
#pragma unroll
                for (int i = 0; i < 2; i++) {
                    mma_bf16(acc[i][2 * p],     ah[i], bh[p][0], bh[p][1]);
                    mma_bf16(acc[i][2 * p + 1], ah[i], bh[p][2], bh[p][3]);
                    mma_bf16(acc[i][2 * p],     ah[i], bl[p][0], bl[p][1]);
                    mma_bf16(acc[i][2 * p + 1], ah[i], bl[p][2], bl[p][3]);
                    mma_bf16(acc[i][2 * p],     al[i], bh[p][0], bh[p][1]);
                    mma_bf16(acc[i][2 * p + 1], al[i], bh[p][2], bh[p][3]);
                }
            }
        }
        __syncthreads();
    }

    const int er = lane >> 2, ec = (lane & 3) * 2;
#pragma unroll
    for (int i = 0; i < 2; i++) {
        const int rbase = row0 + wm * 32 + i * 16 + er;
#pragma unroll
        for (int n = 0; n < 8; n++) {
            const int cc = col0 + wn * 64 + n * 8 + ec;
            if (SPLIT_OUT) {
#pragma unroll
                for (int half = 0; half < 2; half++) {
                    float v0 = acc[i][n][2 * half], v1 = acc[i][n][2 * half + 1];
                    __nv_bfloat162 hv = __floats2bfloat162_rn(v0, v1);
                    __nv_bfloat162 lv = __floats2bfloat162_rn(
                        v0 - __bfloat162float(hv.x), v1 - __bfloat162float(hv.y));
                    size_t off = (size_t)(rbase + half * 8) * 1024 + cc;
                    *(__nv_bfloat162*)(Chi + off) = hv;
                    *(__nv_bfloat162*)(Clo + off) = lv;
                }
            } else {
                float b0 = 0.f, b1 = 0.f;
                if (HAS_BIAS) { b0 = bias[cc]; b1 = bias[cc + 1]; }
                float2 lo_v = make_float2(acc[i][n][0] + b0, acc[i][n][1] + b1);
                float2 hi_v = make_float2(acc[i][n][2] + b0, acc[i][n][3] + b1);
                *(float2*)(C + (size_t)rbase * 1024 + cc)       = lo_v;
                *(float2*)(C + (size_t)(rbase + 8) * 1024 + cc) = hi_v;
            }
        }
    }
}

// ---------------------------------------------------------------------------
// HMMA flash attention (bf16x3 for QK^T and PV, fp32 softmax/accum).
// CTA = (b, h, 128-row q tile); 8 warps, warp = 16 q rows x full 64 kv/d.
// Smem (bf16, 144-B pitch rows): Qh[128] Ql[128] | 2 stages x {Kh,Kl,Vh,Vl}[64]
// Writes ctx directly as hi/lo bf16 into g_Ahi/g_Alo for the output GEMM.
// ---------------------------------------------------------------------------
#define APITCH   144
#define AKV_OFF  36864                 // after Qh(18432)+Ql(18432)
#define AKV_STG  36864                 // 4 arrays * 64 rows * 144
#define AM_OFF   (AKV_OFF + 2 * AKV_STG)
#define ATT_SMEM (AM_OFF + 512)

__global__ __launch_bounds__(256, 1) void attn_hmma(const int* __restrict__ mask)
{
    extern __shared__ char sm[];
    const uint32_t sb = smem_u32(sm);
    const int t = threadIdx.x, lane = t & 31, w = t >> 5;
    const int q0 = blockIdx.x * 128, h = blockIdx.y, b = blockIdx.z;

    const size_t qoff  = (size_t)(b * LL + q0) * D_MODEL + h * HDIM;
    const size_t kvoff = (size_t)b * LL * D_MODEL + h * HDIM;
    const __nv_bfloat16* kvsrc[4] = { g_Kh + kvoff, g_Kl + kvoff,
                                      g_Vh + kvoff, g_Vl + kvoff };

    {   // Q tile (once), committed together with kv stage 0
        const __nv_bfloat16* qsrc[2] = { g_Qh + qoff, g_Ql + qoff };
#pragma unroll
        for (int i = 0; i < 8; i++) {
            int idx = t + i * 256;
            int arr = idx >> 10, row = (idx >> 3) & 127, c = idx & 7;
            cp_async16(sb + arr * 18432 + row * APITCH + c * 16,
                       qsrc[arr] + (size_t)row * D_MODEL + c * 8);
        }
    }
    auto load_kv = [&](int kt) {
        const uint32_t sbase = sb + AKV_OFF + (kt & 1) * AKV_STG;
#pragma unroll
        for (int i = 0; i < 8; i++) {
            int idx = t + i * 256;
            int arr = idx >> 9, row = (idx >> 3) & 63, c = idx & 7;
            cp_async16(sbase + arr * 9216 + row * APITCH + c * 16,
                       kvsrc[arr] + (size_t)(kt * 64 + row) * D_MODEL + c * 8);
        }
        if (t < 64) {
            float bv = mask[b * LL + kt * 64 + t] ? 0.f : -1e30f;
            *(float*)(sm + AM_OFF + (kt & 1) * 256 + t * 4) = bv;
        }
        cp_commit();
    };
    load_kv(0);

    uint32_t qh[4][4], ql[4][4];
    float m0 = -1e30f, m1 = -1e30f, l0 = 0.f, l1 = 0.f;
    float O[8][4];
#pragma unroll
    for (int j = 0; j < 8; j++)
#pragma unroll
        for (int r = 0; r < 4; r++) O[j][r] = 0.f;

    const uint32_t a_addr =
        sb + (uint32_t)((w * 16 + (lane & 15)) * APITCH + (lane >> 4) * 16);
    const uint32_t k_lane =
        (uint32_t)(((lane & 7) + ((lane >> 4) & 1) * 8) * APITCH + ((lane >> 3) & 1) * 16);
    const uint32_t v_lane =
        (uint32_t)(((lane & 7) + ((lane >> 3) & 1) * 8) * APITCH + ((lane >> 4) & 1) * 16);

    for (int kt = 0; kt < LL / 64; kt++) {
        if (kt + 1 < LL / 64) { load_kv(kt + 1); cp_wait<1>(); }
        else                  { cp_wait<0>(); }
        __syncthreads();
        if (kt == 0) {
#pragma unroll
            for (int kd = 0; kd < 4; kd++) {
                ldm_x4(qh[kd], a_addr + kd * 32);
                ldm_x4(ql[kd], a_addr + 18432 + kd * 32);
            }
        }
        const uint32_t kvb = sb + AKV_OFF + (kt & 1) * AKV_STG;

        // ---- S = Q K^T (bf16x3) ----
        float sc_[8][4];
#pragma unroll
        for (int j = 0; j < 8; j++)
#pragma unroll
            for (int r = 0; r < 4; r++) sc_[j][r] = 0.f;
#pragma unroll
        for (int kd = 0; kd < 4; kd++) {
            uint32_t kbh[4][4], kbl[4][4];
#pragma unroll
            for (int g = 0; g < 4; g++) {
                uint32_t ad = kvb + k_lane + (uint32_t)(g * 16 * APITCH) + kd * 32;
                ldm_x4(kbh[g], ad);
                ldm_x4(kbl[g], ad + 9216);
            }
#pragma unroll
            for (int g = 0; g < 4; g++) {
                mma_bf16(sc_[2 * g],     qh[kd], kbh[g][0], kbh[g][1]);
                mma_bf16(sc_[2 * g + 1], qh[kd], kbh[g][2], kbh[g][3]);
                mma_bf16(sc_[2 * g],     qh[kd], kbl[g][0], kbl[g][1]);
                mma_bf16(sc_[2 * g + 1], qh[kd], kbl[g][2], kbl[g][3]);
                mma_bf16(sc_[2 * g],     ql[kd], kbh[g][0], kbh[g][1]);
                mma_bf16(sc_[2 * g + 1], ql[kd], kbh[g][2], kbh[g][3]);
            }
        }

        // ---- online softmax (rows r0 = lane>>2, r1 = r0+8) ----
        const uint32_t mb = sb + AM_OFF + (uint32_t)((kt & 1) * 256 + (lane & 3) * 8);
        float mt0 = -1e30f, mt1 = -1e30f;
#pragma unroll
        for (int j = 0; j < 8; j++) {
            float bx, by;
            asm volatile("ld.shared.v2.f32 {%0,%1}, [%2];"
                         : "=f"(bx), "=f"(by) : "r"(mb + j * 32));
            sc_[j][0] = fmaf(sc_[j][0], 0.125f, bx);
            sc_[j][1] = fmaf(sc_[j][1], 0.125f, by);
            sc_[j][2] = fmaf(sc_[j][2], 0.125f, bx);
            sc_[j][3] = fmaf(sc_[j][3], 0.125f, by);
            mt0 = fmaxf(mt0, fmaxf(sc_[j][0], sc_[j][1]));
            mt1 = fmaxf(mt1, fmaxf(sc_[j][2], sc_[j][3]));
        }
        mt0 = fmaxf(mt0, __shfl_xor_sync(0xffffffffu, mt0, 1));
        mt0 = fmaxf(mt0, __shfl_xor_sync(0xffffffffu, mt0, 2));
        mt1 = fmaxf(mt1, __shfl_xor_sync(0xffffffffu, mt1, 1));
        mt1 = fmaxf(mt1, __shfl_xor_sync(0xffffffffu, mt1, 2));
        const float m0n = fmaxf(m0, mt0), m1n = fmaxf(m1, mt1);
        const float e0 = __expf(m0 - m0n), e1 = __expf(m1 - m1n);
        m0 = m0n; m1 = m1n;
        float rs0 = 0.f, rs1 = 0.f;
#pragma unroll
        for (int j = 0; j < 8; j++) {
            float p0 = __expf(sc_[j][0] - m0n), p1 = __expf(sc_[j][1] - m0n);
            float p2 = __expf(sc_[j][2] - m1n), p3 = __expf(sc_[j][3] - m1n);
            sc_[j][0] = p0; sc_[j][1] = p1; sc_[j][2] = p2; sc_[j][3] = p3;
            rs0 += p0 + p1; rs1 += p2 + p3;
        }
        rs0 += __shfl_xor_sync(0xffffffffu, rs0, 1);
        rs0 += __shfl_xor_sync(0xffffffffu, rs0, 2);
        rs1 += __shfl_xor_sync(0xffffffffu, rs1, 1);
        rs1 += __shfl_xor_sync(0xffffffffu, rs1, 2);
        l0 = l0 * e0 + rs0; l1 = l1 * e1 + rs1;
#pragma unroll
        for (int j = 0; j < 8; j++) {
            O[j][0] *= e0; O[j][1] *= e0; O[j][2] *= e1; O[j][3] *= e1;
        }

        // ---- O += P V (bf16x3, P packed from registers) ----
#pragma unroll
        for (int tk = 0; tk < 4; tk++) {
            uint32_t pah[4], pal[4];
#pragma unroll
            for (int q = 0; q < 4; q++) {
                int j = 2 * tk + (q >> 1);
                float p0 = sc_[j][(q & 1) * 2], p1 = sc_[j][(q & 1) * 2 + 1];
                __nv_bfloat162 hv = __floats2bfloat162_rn(p0, p1);
                __nv_bfloat162 lv = __floats2bfloat162_rn(
                    p0 - __bfloat162float(hv.x), p1 - __bfloat162float(hv.y));
                pah[q] = *(uint32_t*)&hv;
                pal[q] = *(uint32_t*)&lv;
            }
            uint32_t vbh[4][4], vbl[4][4];
#pragma unroll
            for (int dg = 0; dg < 4; dg++) {
                uint32_t ad = kvb + 2 * 9216 + v_lane
                            + (uint32_t)(tk * 16 * APITCH) + dg * 32;
                ldm_x4_t(vbh[dg], ad);
                ldm_x4_t(vbl[dg], ad + 9216);
            }
#pragma unroll
            for (int dg = 0; dg < 4; dg++) {
                mma_bf16(O[2 * dg],     pah, vbh[dg][0], vbh[dg][1]);
                mma_bf16(O[2 * dg + 1], pah, vbh[dg][2], vbh[dg][3]);
                mma_bf16(O[2 * dg],     pah, vbl[dg][0], vbl[dg][1]);
                mma_bf16(O[2 * dg + 1], pah, vbl[dg][2], vbl[dg][3]);
                mma_bf16(O[2 * dg],     pal, vbh[dg][0], vbh[dg][1]);
                mma_bf16(O[2 * dg + 1], pal, vbh[dg][2], vbh[dg][3]);
            }
        }
        __syncthreads();
    }

    // ---- epilogue: normalize, write ctx hi/lo split for the output GEMM ----
    const float inv0 = (m0 > -1e29f && l0 > 0.f) ? 1.f / l0 : 0.f;
    const float inv1 = (m1 > -1e29f && l1 > 0.f) ? 1.f / l1 : 0.f;
    const size_t r0 = (size_t)(b * LL + q0 + w * 16 + (lane >> 2));
    const int cb = h * HDIM + (lane & 3) * 2;
#pragma unroll
    for (int j = 0; j < 8; j++) {
        const int cc = cb + j * 8;
        {
            float v0 = O[j][0] * inv0, v1 = O[j][1] * inv0;
            __nv_bfloat162 hv = __floats2bfloat162_rn(v0, v1);
            __nv_bfloat162 lv = __floats2bfloat162_rn(
                v0 - __bfloat162float(hv.x), v1 - __bfloat162float(hv.y));
            *(__nv_bfloat162*)(g_Ahi + r0 * D_MODEL + cc) = hv;
            *(__nv_bfloat162*)(g_Alo + r0 * D_MODEL + cc) = lv;
        }
        {
            float v0 = O[j][2] * inv1, v1 = O[j][3] * inv1;
            __nv_bfloat162 hv = __floats2bfloat162_rn(v0, v1);
            __nv_bfloat162 lv = __floats2bfloat162_rn(
                v0 - __bfloat162float(hv.x), v1 - __bfloat162float(hv.y));
            *(__nv_bfloat162*)(g_Ahi + (r0 + 8) * D_MODEL + cc) = hv;
            *(__nv_bfloat162*)(g_Alo + (r0 + 8) * D_MODEL + cc) = lv;
        }
    }
}

// ---------------------------------------------------------------------------
extern "C" void kernel_launch(void* const* d_in, const int* in_sizes, int n_in,
                              void* d_out, int out_size)
{
    const float* q    = (const float*)d_in[0];
    const float* k    = (const float*)d_in[1];
    const float* v    = (const float*)d_in[2];
    const int*   mask = (const int*)  d_in[3];
    const float* Wq   = (const float*)d_in[4];
    const float* Wk   = (const float*)d_in[5];
    const float* Wv   = (const float*)d_in[6];
    const float* Wo   = (const float*)d_in[7];
    const float* bo   = (const float*)d_in[8];
    float*       out  = (float*)d_out;

    __nv_bfloat16 *gAhi, *gAlo, *gWhi, *gWlo, *gQh, *gQl, *gKh, *gKl, *gVh, *gVl;
    cudaGetSymbolAddress((void**)&gAhi, g_Ahi);
    cudaGetSymbolAddress((void**)&gAlo, g_Alo);
    cudaGetSymbolAddress((void**)&gWhi, g_Whi);
    cudaGetSymbolAddress((void**)&gWlo, g_Wlo);
    cudaGetSymbolAddress((void**)&gQh, g_Qh);
    cudaGetSymbolAddress((void**)&gQl, g_Ql);
    cudaGetSymbolAddress((void**)&gKh, g_Kh);
    cudaGetSymbolAddress((void**)&gKl, g_Kl);
    cudaGetSymbolAddress((void**)&gVh, g_Vh);
    cudaGetSymbolAddress((void**)&gVl, g_Vl);

    cudaFuncSetAttribute(hmma_gemm<false, true>,
                         cudaFuncAttributeMaxDynamicSharedMemorySize, GSMEM);
    cudaFuncSetAttribute(hmma_gemm<true, false>,
                         cudaFuncAttributeMaxDynamicSharedMemorySize, GSMEM);
    cudaFuncSetAttribute(attn_hmma,
                         cudaFuncAttributeMaxDynamicSharedMemorySize, ATT_SMEM);

    const int n4i = MROWS * D_MODEL / 4;
    const int n4w = D_MODEL * D_MODEL / 4;
    dim3 gg(D_MODEL / 128, MROWS / 128);   // (8, 32)

    // Q projection -> split bf16 output
    split_bf16<<<n4i / 256, 256>>>((const float4*)q,
        (__nv_bfloat162*)gAhi, (__nv_bfloat162*)gAlo, n4i);
    split_bf16<<<n4w / 256, 256>>>((const float4*)Wq,
        (__nv_bfloat162*)gWhi, (__nv_bfloat162*)gWlo, n4w);
    hmma_gemm<false, true><<<gg, 256, GSMEM>>>(gAhi, gAlo, gWhi, gWlo,
                                               nullptr, gQh, gQl, nullptr);
    // K projection
    split_bf16<<<n4i / 256, 256>>>((const float4*)k,
        (__nv_bfloat162*)gAhi, (__nv_bfloat162*)gAlo, n4i);
    split_bf16<<<n4w / 256, 256>>>((const float4*)Wk,
        (__nv_bfloat162*)gWhi, (__nv_bfloat162*)gWlo, n4w);
    hmma_gemm<false, true><<<gg, 256, GSMEM>>>(gAhi, gAlo, gWhi, gWlo,
                                               nullptr, gKh, gKl, nullptr);
    // V projection
    split_bf16<<<n4i / 256, 256>>>((const float4*)v,
        (__nv_bfloat162*)gAhi, (__nv_bfloat162*)gAlo, n4i);
    split_bf16<<<n4w / 256, 256>>>((const float4*)Wv,
        (__nv_bfloat162*)gWhi, (__nv_bfloat162*)gWlo, n4w);
    hmma_gemm<false, true><<<gg, 256, GSMEM>>>(gAhi, gAlo, gWhi, gWlo,
                                               nullptr, gVh, gVl, nullptr);

    // attention (writes ctx split directly into gAhi/gAlo)
    attn_hmma<<<dim3(LL / 128, NHEADS, BB), 256, ATT_SMEM>>>(mask);

    // output projection (fp32 out + bias)
    split_bf16<<<n4w / 256, 256>>>((const float4*)Wo,
        (__nv_bfloat162*)gWhi, (__nv_bfloat162*)gWlo, n4w);
    hmma_gemm<true, false><<<gg, 256, GSMEM>>>(gAhi, gAlo, gWhi, gWlo,
                                               out, nullptr, nullptr, bo);
}

// round 14
// speedup vs baseline: 2.7029x; 1.0378x over previous
#include <cuda_runtime.h>
#include <cuda_bf16.h>
#include <cstdint>
#include <math.h>

#define D_MODEL 1024
#define NHEADS  16
#define HDIM    64
#define BB      2
#define LL      2048
#define MROWS   (BB * LL)   // 4096
#define MD      (MROWS * D_MODEL)
#define DD      (D_MODEL * D_MODEL)

// ---------------- scratch (allocation-free rule: __device__ globals) ---------
__device__ __nv_bfloat16 g_INh[3 * MD];   // split q,k,v inputs
__device__ __nv_bfloat16 g_INl[3 * MD];
__device__ __nv_bfloat16 g_W3h[3 * DD];   // split Wq,Wk,Wv
__device__ __nv_bfloat16 g_W3l[3 * DD];
__device__ __nv_bfloat16 g_Whi[DD];       // split Wo
__device__ __nv_bfloat16 g_Wlo[DD];
__device__ __nv_bfloat16 g_Ahi[MD];       // ctx split (attention -> out proj)
__device__ __nv_bfloat16 g_Alo[MD];
__device__ __nv_bfloat16 g_Qh[MD];
__device__ __nv_bfloat16 g_Ql[MD];
__device__ __nv_bfloat16 g_Kh[MD];
__device__ __nv_bfloat16 g_Kl[MD];
__device__ __nv_bfloat16 g_Vh[MD];
__device__ __nv_bfloat16 g_Vl[MD];

// ---------------------------------------------------------------------------
// baseline-PTX helpers (sm_80-era; tcgen05/TMA are rejected at compute_103)
// ---------------------------------------------------------------------------
static __device__ __forceinline__ uint32_t smem_u32(const void* p) {
    uint32_t a;
    asm("{ .reg .u64 t; cvta.to.shared.u64 t, %1; cvt.u32.u64 %0, t; }"
        : "=r"(a) : "l"(p));
    return a;
}
static __device__ __forceinline__ void cp_async16(uint32_t saddr, const void* gaddr) {
    asm volatile("cp.async.cg.shared.global [%0], [%1], 16;" :: "r"(saddr), "l"(gaddr));
}
static __device__ __forceinline__ void cp_commit() {
    asm volatile("cp.async.commit_group;" ::: "memory");
}
template <int N>
static __device__ __forceinline__ void cp_wait() {
    asm volatile("cp.async.wait_group %0;" :: "n"(N) : "memory");
}
static __device__ __forceinline__ void ldm_x4(uint32_t* r, uint32_t saddr) {
    asm volatile("ldmatrix.sync.aligned.m8n8.x4.shared.b16 {%0,%1,%2,%3}, [%4];"
                 : "=r"(r[0]), "=r"(r[1]), "=r"(r[2]), "=r"(r[3]) : "r"(saddr));
}
static __device__ __forceinline__ void ldm_x4_t(uint32_t* r, uint32_t saddr) {
    asm volatile("ldmatrix.sync.aligned.m8n8.x4.trans.shared.b16 {%0,%1,%2,%3}, [%4];"
                 : "=r"(r[0]), "=r"(r[1]), "=r"(r[2]), "=r"(r[3]) : "r"(saddr));
}
static __device__ __forceinline__ void mma_bf16(float* c, const uint32_t* a,
                                                uint32_t b0, uint32_t b1) {
    asm volatile(
        "mma.sync.aligned.m16n8k16.row.col.f32.bf16.bf16.f32 "
        "{%0,%1,%2,%3}, {%4,%5,%6,%7}, {%8,%9}, {%0,%1,%2,%3};"
        : "+f"(c[0]), "+f"(c[1]), "+f"(c[2]), "+f"(c[3])
        : "r"(a[0]), "r"(a[1]), "r"(a[2]), "r"(a[3]), "r"(b0), "r"(b1));
}

// ---------------------------------------------------------------------------
// fp32 -> bf16 hi/lo split
// ---------------------------------------------------------------------------
__global__ void split_bf16(const float4* __restrict__ in,
                           __nv_bfloat162* __restrict__ hi,
                           __nv_bfloat162* __restrict__ lo, int n4)
{
    int i = blockIdx.x * blockDim.x + threadIdx.x;
    if (i >= n4) return;
    float4 x = in[i];
    __nv_bfloat16 h0 = __float2bfloat16(x.x), h1 = __float2bfloat16(x.y);
    __nv_bfloat16 h2 = __float2bfloat16(x.z), h3 = __float2bfloat16(x.w);
    __nv_bfloat16 l0 = __float2bfloat16(x.x - __bfloat162float(h0));
    __nv_bfloat16 l1 = __float2bfloat16(x.y - __bfloat162float(h1));
    __nv_bfloat16 l2 = __float2bfloat16(x.z - __bfloat162float(h2));
    __nv_bfloat16 l3 = __float2bfloat16(x.w - __bfloat162float(h3));
    hi[2 * i]     = __nv_bfloat162(h0, h1);
    hi[2 * i + 1] = __nv_bfloat162(h2, h3);
    lo[2 * i]     = __nv_bfloat162(l0, l1);
    lo[2 * i + 1] = __nv_bfloat162(l2, l3);
}

// ---------------------------------------------------------------------------
// HMMA GEMM (bf16x3), CTA tile 128x256, 512 threads (16 warps, 4x4 warp grid),
// BK=32, 3-stage cp.async pipeline, optionally batched over blockIdx.z.
// Smem stage: A: op*10240 + row*80 + c*16 (128 rows)
//             B: 20480 + op*20480 + row*80 + c*16 (256 rows)
// stage = 61440 B, 3 stages = 184320 B.
// ---------------------------------------------------------------------------
#define STG2   61440
#define GSMEM2 (3 * STG2)

template <bool SPLIT_OUT>
__global__ __launch_bounds__(512, 1) void hmma_gemm2(
    const __nv_bfloat16* __restrict__ Abase_hi,
    const __nv_bfloat16* __restrict__ Abase_lo,
    const __nv_bfloat16* __restrict__ Wbase_hi,
    const __nv_bfloat16* __restrict__ Wbase_lo,
    __nv_bfloat16* __restrict__ Chi0, __nv_bfloat16* __restrict__ Clo0,
    __nv_bfloat16* __restrict__ Chi1, __nv_bfloat16* __restrict__ Clo1,
    __nv_bfloat16* __restrict__ Chi2, __nv_bfloat16* __restrict__ Clo2,
    float* __restrict__ C, const float* __restrict__ bias)
{
    extern __shared__ char sm[];
    const uint32_t sb = smem_u32(sm);
    const int t = threadIdx.x;
    const int lane = t & 31, wid = t >> 5;
    const int wm = wid & 3, wn = wid >> 2;      // 4x4 warp grid: 32 rows x 64 cols
    const int row0 = blockIdx.y * 128, col0 = blockIdx.x * 256;
    const int z = blockIdx.z;

    const __nv_bfloat16* srcA[2] = {
        Abase_hi + (size_t)z * MD + (size_t)row0 * 1024,
        Abase_lo + (size_t)z * MD + (size_t)row0 * 1024 };
    const __nv_bfloat16* srcB[2] = {
        Wbase_hi + (size_t)z * DD + (size_t)col0 * 1024,
        Wbase_lo + (size_t)z * DD + (size_t)col0 * 1024 };

    auto load_stage = [&](int s) {
        const int k0 = s * 32;
        const uint32_t sbase = sb + (uint32_t)((s % 3) * STG2);
#pragma unroll
        for (int i = 0; i < 6; i++) {
            int idx = t + i * 512;          // 0..3071
            if (idx < 1024) {               // A: 2 ops x 128 rows x 4 chunks
                int op = idx >> 9, r = (idx >> 2) & 127, c = idx & 3;
                cp_async16(sbase + op * 10240 + r * 80 + c * 16,
                           srcA[op] + (size_t)r * 1024 + k0 + c * 8);
            } else {                        // B: 2 ops x 256 rows x 4 chunks
                int j = idx - 1024;
                int op = j >> 10, r = (j >> 2) & 255, c = j & 3;
                cp_async16(sbase + 20480 + op * 20480 + r * 80 + c * 16,
                           srcB[op] + (size_t)r * 1024 + k0 + c * 8);
            }
        }
        cp_commit();
    };

    const uint32_t a_lane = (uint32_t)((wm * 32 + (lane & 15)) * 80 + (lane >> 4) * 16);
    const uint32_t b_lane = (uint32_t)((wn * 64 + (lane & 7) + ((lane >> 4) & 1) * 8) * 80
                                       + ((lane >> 3) & 1) * 16);

    float acc[2][8][4];
#pragma unroll
    for (int i = 0; i < 2; i++)
#pragma unroll
        for (int n = 0; n < 8; n++)
#pragma unroll
            for (int j = 0; j < 4; j++) acc[i][n][j] = 0.f;

    load_stage(0);
    load_stage(1);

    for (int s = 0; s < 32; s++) {
        if (s + 2 < 32)      { load_stage(s + 2); cp_wait<2>(); }
        else if (s + 1 < 32) { cp_wait<1>(); }
        else                 { cp_wait<0>(); }
        __syncthreads();

        const uint32_t sbase = sb + (uint32_t)((s % 3) * STG2);
#pragma unroll
        for (int ks = 0; ks < 2; ks++) {
            const uint32_t ksb = ks * 32;
            uint32_t ah[2][4], al[2][4], bh[4][4], bl[4][4];
#pragma unroll
            for (int i = 0; i < 2; i++) {
                uint32_t base = sbase + a_lane + (uint32_t)(i * 16 * 80) + ksb;
                ldm_x4(ah[i], base);
                ldm_x4(al[i], base + 10240);
            }
#pragma unroll
            for (int p = 0; p < 4; p++) {
                uint32_t base = sbase + 20480 + b_lane + (uint32_t)(p * 16 * 80) + ksb;
                ldm_x4(bh[p], base);
                ldm_x4(bl[p], base + 20480);
            }
#pragma unroll
            for (int p = 0; p < 4; p++) {
#pragma unroll
                for (int i = 0; i < 2; i++) {
                    mma_bf16(acc[i][2 * p],     ah[i], bh[p][0], bh[p][1]);
                    mma_bf16(acc[i][2 * p + 1], ah[i], bh[p][2], bh[p][3]);
                    mma_bf16(acc[i][2 * p],     ah[i], bl[p][0], bl[p][1]);
                    mma_bf16(acc[i][2 * p + 1], ah[i], bl[p][2], bl[p][3]);
                    mma_bf16(acc[i][2 * p],     al[i], bh[p][0], bh[p][1]);
                    mma_bf16(acc[i][2 * p + 1], al[i], bh[p][2], bh[p][3]);
                }
            }
        }
        __syncthreads();
    }

    __nv_bfloat16* Chi = (z == 0) ? Chi0 : (z == 1) ? Chi1 : Chi2;
    __nv_bfloat16* Clo = (z == 0) ? Clo0 : (z == 1) ? Clo1 : Clo2;

    const int er = lane >> 2, ec = (lane & 3) * 2;
#pragma unroll
    for (int i = 0; i < 2; i++) {
        const int rbase = row0 + wm * 32 + i * 16 + er;
#pragma unroll
        for (int n = 0; n < 8; n++) {
            const int cc = col0 + wn * 64 + n * 8 + ec;
            if (SPLIT_OUT) {
#pragma unroll
                for (int half = 0; half < 2; half++) {
                    float v0 = acc[i][n][2 * half], v1 = acc[i][n][2 * half + 1];
                    __nv_bfloat162 hv = __floats2bfloat162_rn(v0, v1);
                    __nv_bfloat162 lv = __floats2bfloat162_rn(
                        v0 - __bfloat162float(hv.x), v1 - __bfloat162float(hv.y));
                    size_t off = (size_t)(rbase + half * 8) * 1024 + cc;
                    *(__nv_bfloat162*)(Chi + off) = hv;
                    *(__nv_bfloat162*)(Clo + off) = lv;
                }
            } else {
                float b0 = bias[cc], b1 = bias[cc + 1];
                float2 lo_v = make_float2(acc[i][n][0] + b0, acc[i][n][1] + b1);
                float2 hi_v = make_float2(acc[i][n][2] + b0, acc[i][n][3] + b1);
                *(float2*)(C + (size_t)rbase * 1024 + cc)       = lo_v;
                *(float2*)(C + (size_t)(rbase + 8) * 1024 + cc) = hi_v;
            }
        }
    }
}

// ---------------------------------------------------------------------------
// HMMA flash attention (bf16x3 for QK^T and PV, fp32 softmax/accum).
// CTA = (b, h, 128-row q tile); 8 warps, warp = 16 q rows x full 64 kv/d.
// (unchanged from R11 — measured 322 TF/s effective)
// ---------------------------------------------------------------------------
#define APITCH   144
#define AKV_OFF  36864
#define AKV_STG  36864
#define AM_OFF   (AKV_OFF + 2 * AKV_STG)
#define ATT_SMEM (AM_OFF + 512)

__global__ __launch_bounds__(256, 1) void attn_hmma(const int* __restrict__ mask)
{
    extern __shared__ char sm[];
    const uint32_t sb = smem_u32(sm);
    const int t = threadIdx.x, lane = t & 31, w = t >> 5;
    const int q0 = blockIdx.x * 128, h = blockIdx.y, b = blockIdx.z;

    const size_t qoff  = (size_t)(b * LL + q0) * D_MODEL + h * HDIM;
    const size_t kvoff = (size_t)b * LL * D_MODEL + h * HDIM;
    const __nv_bfloat16* kvsrc[4] = { g_Kh + kvoff, g_Kl + kvoff,
                                      g_Vh + kvoff, g_Vl + kvoff };

    {
        const __nv_bfloat16* qsrc[2] = { g_Qh + qoff, g_Ql + qoff };
#pragma unroll
        for (int i = 0; i < 8; i++) {
            int idx = t + i * 256;
            int arr = idx >> 10, row = (idx >> 3) & 127, c = idx & 7;
            cp_async16(sb + arr * 18432 + row * APITCH + c * 16,
                       qsrc[arr] + (size_t)row * D_MODEL + c * 8);
        }
    }
    auto load_kv = [&](int kt) {
        const uint32_t sbase = sb + AKV_OFF + (kt & 1) * AKV_STG;
#pragma unroll
        for (int i = 0; i < 8; i++) {
            int idx = t + i * 256;
            int arr = idx >> 9, row = (idx >> 3) & 63, c = idx & 7;
            cp_async16(sbase + arr * 9216 + row * APITCH + c * 16,
                       kvsrc[arr] + (size_t)(kt * 64 + row) * D_MODEL + c * 8);
        }
        if (t < 64) {
            float bv = mask[b * LL + kt * 64 + t] ? 0.f : -1e30f;
            *(float*)(sm + AM_OFF + (kt & 1) * 256 + t * 4) = bv;
        }
        cp_commit();
    };
    load_kv(0);

    uint32_t qh[4][4], ql[4][4];
    float m0 = -1e30f, m1 = -1e30f, l0 = 0.f, l1 = 0.f;
    float O[8][4];
#pragma unroll
    for (int j = 0; j < 8; j++)
#pragma unroll
        for (int r = 0; r < 4; r++) O[j][r] = 0.f;

    const uint32_t a_addr =
        sb + (uint32_t)((w * 16 + (lane & 15)) * APITCH + (lane >> 4) * 16);
    const uint32_t k_lane =
        (uint32_t)(((lane & 7) + ((lane >> 4) & 1) * 8) * APITCH + ((lane >> 3) & 1) * 16);
    const uint32_t v_lane =
        (uint32_t)(((lane & 7) + ((lane >> 3) & 1) * 8) * APITCH + ((lane >> 4) & 1) * 16);

    for (int kt = 0; kt < LL / 64; kt++) {
        if (kt + 1 < LL / 64) { load_kv(kt + 1); cp_wait<1>(); }
        else                  { cp_wait<0>(); }
        __syncthreads();
        if (kt == 0) {
#pragma unroll
            for (int kd = 0; kd < 4; kd++) {
                ldm_x4(qh[kd], a_addr + kd * 32);
                ldm_x4(ql[kd], a_addr + 18432 + kd * 32);
            }
        }
        const uint32_t kvb = sb + AKV_OFF + (kt & 1) * AKV_STG;

        float sc_[8][4];
#pragma unroll
        for (int j = 0; j < 8; j++)
#pragma unroll
            for (int r = 0; r < 4; r++) sc_[j][r] = 0.f;
#pragma unroll
        for (int kd = 0; kd < 4; kd++) {
            uint32_t kbh[4][4], kbl[4][4];
#pragma unroll
            for (int g = 0; g < 4; g++) {
                uint32_t ad = kvb + k_lane + (uint32_t)(g * 16 * APITCH) + kd * 32;
                ldm_x4(kbh[g], ad);
                ldm_x4(kbl[g], ad + 9216);
            }
#pragma unroll
            for (int g = 0; g < 4; g++) {
                mma_bf16(sc_[2 * g],     qh[kd], kbh[g][0], kbh[g][1]);
                mma_bf16(sc_[2 * g + 1], qh[kd], kbh[g][2], kbh[g][3]);
                mma_bf16(sc_[2 * g],     qh[kd], kbl[g][0], kbl[g][1]);
                mma_bf16(sc_[2 * g + 1], qh[kd], kbl[g][2], kbl[g][3]);
                mma_bf16(sc_[2 * g],     ql[kd], kbh[g][0], kbh[g][1]);
                mma_bf16(sc_[2 * g + 1], ql[kd], kbh[g][2], kbh[g][3]);
            }
        }

        const uint32_t mb = sb + AM_OFF + (uint32_t)((kt & 1) * 256 + (lane & 3) * 8);
        float mt0 = -1e30f, mt1 = -1e30f;
#pragma unroll
        for (int j = 0; j < 8; j++) {
            float bx, by;
            asm volatile("ld.shared.v2.f32 {%0,%1}, [%2];"
                         : "=f"(bx), "=f"(by) : "r"(mb + j * 32));
            sc_[j][0] = fmaf(sc_[j][0], 0.125f, bx);
            sc_[j][1] = fmaf(sc_[j][1], 0.125f, by);
            sc_[j][2] = fmaf(sc_[j][2], 0.125f, bx);
            sc_[j][3] = fmaf(sc_[j][3], 0.125f, by);
            mt0 = fmaxf(mt0, fmaxf(sc_[j][0], sc_[j][1]));
            mt1 = fmaxf(mt1, fmaxf(sc_[j][2], sc_[j][3]));
        }
        mt0 = fmaxf(mt0, __shfl_xor_sync(0xffffffffu, mt0, 1));
        mt0 = fmaxf(mt0, __shfl_xor_sync(0xffffffffu, mt0, 2));
        mt1 = fmaxf(mt1, __shfl_xor_sync(0xffffffffu, mt1, 1));
        mt1 = fmaxf(mt1, __shfl_xor_sync(0xffffffffu, mt1, 2));
        const float m0n = fmaxf(m0, mt0), m1n = fmaxf(m1, mt1);
        const float e0 = __expf(m0 - m0n), e1 = __expf(m1 - m1n);
        m0 = m0n; m1 = m1n;
        float rs0 = 0.f, rs1 = 0.f;
#pragma unroll
        for (int j = 0; j < 8; j++) {
            float p0 = __expf(sc_[j][0] - m0n), p1 = __expf(sc_[j][1] - m0n);
            float p2 = __expf(sc_[j][2] - m1n), p3 = __expf(sc_[j][3] - m1n);
            sc_[j][0] = p0; sc_[j][1] = p1; sc_[j][2] = p2; sc_[j][3] = p3;
            rs0 += p0 + p1; rs1 += p2 + p3;
        }
        rs0 += __shfl_xor_sync(0xffffffffu, rs0, 1);
        rs0 += __shfl_xor_sync(0xffffffffu, rs0, 2);
        rs1 += __shfl_xor_sync(0xffffffffu, rs1, 1);
        rs1 += __shfl_xor_sync(0xffffffffu, rs1, 2);
        l0 = l0 * e0 + rs0; l1 = l1 * e1 + rs1;
#pragma unroll
        for (int j = 0; j < 8; j++) {
            O[j][0] *= e0; O[j][1] *= e0; O[j][2] *= e1; O[j][3] *= e1;
        }

#pragma unroll
        for (int tk = 0; tk < 4; tk++) {
            uint32_t pah[4], pal[4];
#pragma unroll
            for (int q = 0; q < 4; q++) {
                int j = 2 * tk + (q >> 1);
                float p0 = sc_[j][(q & 1) * 2], p1 = sc_[j][(q & 1) * 2 + 1];
                __nv_bfloat162 hv = __floats2bfloat162_rn(p0, p1);
                __nv_bfloat162 lv = __floats2bfloat162_rn(
                    p0 - __bfloat162float(hv.x), p1 - __bfloat162float(hv.y));
                pah[q] = *(uint32_t*)&hv;
                pal[q] = *(uint32_t*)&lv;
            }
            uint32_t vbh[4][4], vbl[4][4];
#pragma unroll
            for (int dg = 0; dg < 4; dg++) {
                uint32_t ad = kvb + 2 * 9216 + v_lane
                            + (uint32_t)(tk * 16 * APITCH) + dg * 32;
                ldm_x4_t(vbh[dg], ad);
                ldm_x4_t(vbl[dg], ad + 9216);
            }
#pragma unroll
            for (int dg = 0; dg < 4; dg++) {
                mma_bf16(O[2 * dg],     pah, vbh[dg][0], vbh[dg][1]);
                mma_bf16(O[2 * dg + 1], pah, vbh[dg][2], vbh[dg][3]);
                mma_bf16(O[2 * dg],     pah, vbl[dg][0], vbl[dg][1]);
                mma_bf16(O[2 * dg + 1], pah, vbl[dg][2], vbl[dg][3]);
                mma_bf16(O[2 * dg],     pal, vbh[dg][0], vbh[dg][1]);
                mma_bf16(O[2 * dg + 1], pal, vbh[dg][2], vbh[dg][3]);
            }
        }
        __syncthreads();
    }

    const float inv0 = (m0 > -1e29f && l0 > 0.f) ? 1.f / l0 : 0.f;
    const float inv1 = (m1 > -1e29f && l1 > 0.f) ? 1.f / l1 : 0.f;
    const size_t r0 = (size_t)(b * LL + q0 + w * 16 + (lane >> 2));
    const int cb = h * HDIM + (lane & 3) * 2;
#pragma unroll
    for (int j = 0; j < 8; j++) {
        const int cc = cb + j * 8;
        {
            float v0 = O[j][0] * inv0, v1 = O[j][1] * inv0;
            __nv_bfloat162 hv = __floats2bfloat162_rn(v0, v1);
            __nv_bfloat162 lv = __floats2bfloat162_rn(
                v0 - __bfloat162float(hv.x), v1 - __bfloat162float(hv.y));
            *(__nv_bfloat162*)(g_Ahi + r0 * D_MODEL + cc) = hv;
            *(__nv_bfloat162*)(g_Alo + r0 * D_MODEL + cc) = lv;
        }
        {
            float v0 = O[j][2] * inv1, v1 = O[j][3] * inv1;
            __nv_bfloat162 hv = __floats2bfloat162_rn(v0, v1);
            __nv_bfloat162 lv = __floats2bfloat162_rn(
                v0 - __bfloat162float(hv.x), v1 - __bfloat162float(hv.y));
            *(__nv_bfloat162*)(g_Ahi + (r0 + 8) * D_MODEL + cc) = hv;
            *(__nv_bfloat162*)(g_Alo + (r0 + 8) * D_MODEL + cc) = lv;
        }
    }
}

// ---------------------------------------------------------------------------
extern "C" void kernel_launch(void* const* d_in, const int* in_sizes, int n_in,
                              void* d_out, int out_size)
{
    const float* q    = (const float*)d_in[0];
    const float* k    = (const float*)d_in[1];
    const float* v    = (const float*)d_in[2];
    const int*   mask = (const int*)  d_in[3];
    const float* Wq   = (const float*)d_in[4];
    const float* Wk   = (const float*)d_in[5];
    const float* Wv   = (const float*)d_in[6];
    const float* Wo   = (const float*)d_in[7];
    const float* bo   = (const float*)d_in[8];
    float*       out  = (float*)d_out;

    __nv_bfloat16 *gINh, *gINl, *gW3h, *gW3l, *gWhi, *gWlo, *gAhi, *gAlo;
    __nv_bfloat16 *gQh, *gQl, *gKh, *gKl, *gVh, *gVl;
    cudaGetSymbolAddress((void**)&gINh, g_INh);
    cudaGetSymbolAddress((void**)&gINl, g_INl);
    cudaGetSymbolAddress((void**)&gW3h, g_W3h);
    cudaGetSymbolAddress((void**)&gW3l, g_W3l);
    cudaGetSymbolAddress((void**)&gWhi, g_Whi);
    cudaGetSymbolAddress((void**)&gWlo, g_Wlo);
    cudaGetSymbolAddress((void**)&gAhi, g_Ahi);
    cudaGetSymbolAddress((void**)&gAlo, g_Alo);
    cudaGetSymbolAddress((void**)&gQh, g_Qh);
    cudaGetSymbolAddress((void**)&gQl, g_Ql);
    cudaGetSymbolAddress((void**)&gKh, g_Kh);
    cudaGetSymbolAddress((void**)&gKl, g_Kl);
    cudaGetSymbolAddress((void**)&gVh, g_Vh);
    cudaGetSymbolAddress((void**)&gVl, g_Vl);

    cudaFuncSetAttribute(hmma_gemm2<true>,
                         cudaFuncAttributeMaxDynamicSharedMemorySize, GSMEM2);
    cudaFuncSetAttribute(hmma_gemm2<false>,
                         cudaFuncAttributeMaxDynamicSharedMemorySize, GSMEM2);
    cudaFuncSetAttribute(attn_hmma,
                         cudaFuncAttributeMaxDynamicSharedMemorySize, ATT_SMEM);

    const int n4i = MD / 4;
    const int n4w = DD / 4;

    // split q,k,v inputs and Wq,Wk,Wv weights into batched buffers
    const float* ins[3] = { q, k, v };
    const float* ws[3]  = { Wq, Wk, Wv };
    for (int z = 0; z < 3; z++) {
        split_bf16<<<n4i / 256, 256>>>((const float4*)ins[z],
            (__nv_bfloat162*)(gINh + (size_t)z * MD),
            (__nv_bfloat162*)(gINl + (size_t)z * MD), n4i);
        split_bf16<<<n4w / 256, 256>>>((const float4*)ws[z],
            (__nv_bfloat162*)(gW3h + (size_t)z * DD),
            (__nv_bfloat162*)(gW3l + (size_t)z * DD), n4w);
    }

    // batched Q/K/V projections: grid (4, 32, 3)
    hmma_gemm2<true><<<dim3(D_MODEL / 256, MROWS / 128, 3), 512, GSMEM2>>>(
        gINh, gINl, gW3h, gW3l,
        gQh, gQl, gKh, gKl, gVh, gVl, nullptr, nullptr);

    // attention (writes ctx split into gAhi/gAlo)
    attn_hmma<<<dim3(LL / 128, NHEADS, BB), 256, ATT_SMEM>>>(mask);

    // output projection
    split_bf16<<<n4w / 256, 256>>>((const float4*)Wo,
        (__nv_bfloat162*)gWhi, (__nv_bfloat162*)gWlo, n4w);
    hmma_gemm2<false><<<dim3(D_MODEL / 256, MROWS / 128, 1), 512, GSMEM2>>>(
        gAhi, gAlo, gWhi, gWlo,
        nullptr, nullptr, nullptr, nullptr, nullptr, nullptr, out, bo);
}